// round 3
// baseline (speedup 1.0000x reference)
#include <cuda_runtime.h>

// EntmaxBisect: alpha=1.5, 50-iter bisection over last dim (4096), rows = 8*2048 = 16384.
//
// Reduction: with p = 1/4095, every positive term (Xs_i - t)^p lies in
// (0.975, 1], so sum(Z) >= 1  <=>  count(Xs > t) >= 2  <=>  second_largest(Xs) > t.
// The bisection depends only on the row's top-2, replicated bit-exactly on the
// reference's fp32 lattice with a scalar loop (returns the final TESTED t,
// exactly as the reference does).
//
// Z is computed ONCE per element with __powf (MUFU LG2/EX2): u = S - t is a
// difference of fp32 values of magnitude ~1, so u is 0 or >= ~6e-8 (normal) —
// FTZ in MUFU cannot flip mask membership; value error ~1e-5 << 1e-3 tol.

#define D        4096
#define THREADS  512
#define PER_THR  8           // D / THREADS
#define NWARPS   16
#define N_ITER   50

__global__ __launch_bounds__(THREADS, 4)
void entmax_bisect_kernel(const float* __restrict__ X, float* __restrict__ out)
{
    const unsigned long long row = blockIdx.x;
    const float* __restrict__ xrow = X + row * (unsigned long long)D;
    float* __restrict__ orow = out + row * (unsigned long long)D;

    const int tid  = threadIdx.x;
    const int lane = tid & 31;
    const int wid  = tid >> 5;

    // ---- load 8 floats/thread (2x float4, streaming), Xs = 0.5*X (exact) ----
    const float4* __restrict__ x4 = reinterpret_cast<const float4*>(xrow);
    float4 v0 = __ldcs(&x4[tid]);
    float4 v1 = __ldcs(&x4[tid + THREADS]);
    float xs[PER_THR];
    xs[0] = 0.5f * v0.x;  xs[1] = 0.5f * v0.y;
    xs[2] = 0.5f * v0.z;  xs[3] = 0.5f * v0.w;
    xs[4] = 0.5f * v1.x;  xs[5] = 0.5f * v1.y;
    xs[6] = 0.5f * v1.z;  xs[7] = 0.5f * v1.w;

    // ---- per-thread top-2, branchless (3 min/max per element) ----
    float m1 = -__int_as_float(0x7f800000);   // -inf
    float m2 = m1;
    #pragma unroll
    for (int k = 0; k < PER_THR; k++) {
        float v  = xs[k];
        float lo = fminf(m1, v);
        m1 = fmaxf(m1, v);
        m2 = fmaxf(m2, lo);
    }

    // ---- warp top-2 reduce ----
    #pragma unroll
    for (int off = 16; off > 0; off >>= 1) {
        float b1 = __shfl_down_sync(0xffffffffu, m1, off);
        float b2 = __shfl_down_sync(0xffffffffu, m2, off);
        float lo = fminf(m1, b1);
        m1 = fmaxf(m1, b1);
        m2 = fmaxf(fmaxf(m2, b2), lo);
    }

    __shared__ float sm1[NWARPS];
    __shared__ float sm2[NWARPS];
    __shared__ float ssum[NWARPS];
    __shared__ float sbc;        // final t

    if (lane == 0) { sm1[wid] = m1; sm2[wid] = m2; }
    __syncthreads();

    if (tid == 0) {
        float M = sm1[0], S = sm2[0];
        #pragma unroll
        for (int w = 1; w < NWARPS; w++) {
            float b1 = sm1[w];
            float lo = fminf(M, b1);
            M = fmaxf(M, b1);
            S = fmaxf(fmaxf(S, sm2[w]), lo);
        }
        // ---- scalar fp32 bisection, bit-faithful to the reference lattice ----
        float tmin = M - 1.0f;
        float tmax = M - 0.015625f;          // M - 4096^(1-1.5), exact constant
        float diff = tmax - tmin;
        float t = tmin;
        #pragma unroll 1
        for (int i = 0; i < N_ITER; i++) {
            diff = diff * 0.5f;
            t = tmin + diff;
            if (S > t) tmin = t;             // == (sum(Z)-1 >= 0)
        }
        sbc = t;                             // final TESTED t, as in reference
    }
    __syncthreads();

    const float t = sbc;
    const float p = 1.0f / 4095.0f;          // == fp32(1/(d-1))

    // ---- compute Z once (branchless fast pow), keep in registers, sum ----
    float lsum = 0.0f;
    #pragma unroll
    for (int k = 0; k < PER_THR; k++) {
        float u = xs[k] - t;
        float z = __powf(u, p);              // MUFU path; u<=0 handled by select
        z = (u > 0.0f) ? z : 0.0f;
        xs[k] = z;
        lsum += z;
    }
    #pragma unroll
    for (int off = 16; off > 0; off >>= 1)
        lsum += __shfl_down_sync(0xffffffffu, lsum, off);
    if (lane == 0) ssum[wid] = lsum;
    __syncthreads();

    // all threads redundantly sum 16 warp partials (15 FADD, no extra barrier)
    float tot = 0.0f;
    #pragma unroll
    for (int w = 0; w < NWARPS; w++) tot += ssum[w];
    const float inv = 1.0f / tot;

    // ---- write normalized Z, coalesced streaming float4 stores ----
    float4* __restrict__ o4 = reinterpret_cast<float4*>(orow);
    float4 r0, r1;
    r0.x = xs[0] * inv;  r0.y = xs[1] * inv;
    r0.z = xs[2] * inv;  r0.w = xs[3] * inv;
    r1.x = xs[4] * inv;  r1.y = xs[5] * inv;
    r1.z = xs[6] * inv;  r1.w = xs[7] * inv;
    __stcs(&o4[tid], r0);
    __stcs(&o4[tid + THREADS], r1);
}

extern "C" void kernel_launch(void* const* d_in, const int* in_sizes, int n_in,
                              void* d_out, int out_size)
{
    const float* X = (const float*)d_in[0];
    float* out = (float*)d_out;
    const int n = in_sizes[0];          // 8*2048*4096
    const int rows = n / D;             // 16384
    entmax_bisect_kernel<<<rows, THREADS>>>(X, out);
}

// round 4
// speedup vs baseline: 1.5462x; 1.5462x over previous
#include <cuda_runtime.h>

// EntmaxBisect: alpha=1.5, 50-iter bisection over last dim (4096), rows = 8*2048 = 16384.
//
// Reduction: with p = 1/4095, every positive term (Xs_i - t)^p lies in
// (0.975, 1], so sum(Z) >= 1  <=>  count(Xs > t) >= 2  <=>  second_largest(Xs) > t.
// The bisection depends only on the row's top-2, replicated bit-exactly on the
// reference's fp32 lattice with a scalar loop (returns the final TESTED t).
//
// Top-2 is computed on raw X and scaled by 0.5 afterwards (exact, monotone).
// Z is computed ONCE per element; the pow is BRANCHED so the ~99.95% of warps
// with no active lane skip the MUFU path entirely (round-3 lesson: making it
// branchless regressed 108->156us by saturating MUFU/issue).

#define D        4096
#define THREADS  512
#define PER_THR  8           // D / THREADS
#define NWARPS   16
#define N_ITER   50

__global__ __launch_bounds__(THREADS, 4)
void entmax_bisect_kernel(const float* __restrict__ X, float* __restrict__ out)
{
    const unsigned long long row = blockIdx.x;
    const float* __restrict__ xrow = X + row * (unsigned long long)D;
    float* __restrict__ orow = out + row * (unsigned long long)D;

    const int tid  = threadIdx.x;
    const int lane = tid & 31;
    const int wid  = tid >> 5;

    // ---- load 8 floats/thread (2x float4, coalesced), keep RAW X ----
    const float4* __restrict__ x4 = reinterpret_cast<const float4*>(xrow);
    float4 v0 = x4[tid];
    float4 v1 = x4[tid + THREADS];
    float xs[PER_THR];
    xs[0] = v0.x;  xs[1] = v0.y;  xs[2] = v0.z;  xs[3] = v0.w;
    xs[4] = v1.x;  xs[5] = v1.y;  xs[6] = v1.z;  xs[7] = v1.w;

    // ---- per-thread top-2 of raw X, branchless (3 min/max per element) ----
    float m1 = -__int_as_float(0x7f800000);   // -inf
    float m2 = m1;
    #pragma unroll
    for (int k = 0; k < PER_THR; k++) {
        float v  = xs[k];
        float lo = fminf(m1, v);
        m1 = fmaxf(m1, v);
        m2 = fmaxf(m2, lo);
    }

    // ---- warp top-2 reduce ----
    #pragma unroll
    for (int off = 16; off > 0; off >>= 1) {
        float b1 = __shfl_down_sync(0xffffffffu, m1, off);
        float b2 = __shfl_down_sync(0xffffffffu, m2, off);
        float lo = fminf(m1, b1);
        m1 = fmaxf(m1, b1);
        m2 = fmaxf(fmaxf(m2, b2), lo);
    }

    __shared__ float sm1[NWARPS];
    __shared__ float sm2[NWARPS];
    __shared__ float ssum[NWARPS];
    __shared__ float sbc;        // final t

    if (lane == 0) { sm1[wid] = m1; sm2[wid] = m2; }
    __syncthreads();

    if (tid == 0) {
        float M = sm1[0], S = sm2[0];
        #pragma unroll
        for (int w = 1; w < NWARPS; w++) {
            float b1 = sm1[w];
            float lo = fminf(M, b1);
            M = fmaxf(M, b1);
            S = fmaxf(fmaxf(S, sm2[w]), lo);
        }
        M *= 0.5f;                            // exact: top-2 of Xs = 0.5 * top-2 of X
        S *= 0.5f;
        // ---- scalar fp32 bisection, bit-faithful to the reference lattice ----
        float tmin = M - 1.0f;
        float tmax = M - 0.015625f;          // M - 4096^(1-1.5), exact constant
        float diff = tmax - tmin;
        float t = tmin;
        #pragma unroll 1
        for (int i = 0; i < N_ITER; i++) {
            diff = diff * 0.5f;
            t = tmin + diff;
            if (S > t) tmin = t;             // == (sum(Z)-1 >= 0)
        }
        sbc = t;                             // final TESTED t, as in reference
    }
    __syncthreads();

    const float t = sbc;
    const float p = 1.0f / 4095.0f;          // == fp32(1/(d-1))

    // ---- compute Z once (branch-guarded fast pow), keep in regs, sum ----
    float lsum = 0.0f;
    #pragma unroll
    for (int k = 0; k < PER_THR; k++) {
        float u = fmaf(0.5f, xs[k], -t);     // == (0.5*x exact) - t, single round
        float z = 0.0f;
        if (u > 0.0f) z = __powf(u, p);      // rare path: ~2 lanes per ROW
        xs[k] = z;
        lsum += z;
    }
    #pragma unroll
    for (int off = 16; off > 0; off >>= 1)
        lsum += __shfl_down_sync(0xffffffffu, lsum, off);
    if (lane == 0) ssum[wid] = lsum;
    __syncthreads();

    // all threads redundantly sum 16 warp partials (15 FADD, no extra barrier)
    float tot = 0.0f;
    #pragma unroll
    for (int w = 0; w < NWARPS; w++) tot += ssum[w];
    const float inv = 1.0f / tot;

    // ---- write normalized Z, coalesced float4 stores ----
    float4* __restrict__ o4 = reinterpret_cast<float4*>(orow);
    float4 r0, r1;
    r0.x = xs[0] * inv;  r0.y = xs[1] * inv;
    r0.z = xs[2] * inv;  r0.w = xs[3] * inv;
    r1.x = xs[4] * inv;  r1.y = xs[5] * inv;
    r1.z = xs[6] * inv;  r1.w = xs[7] * inv;
    o4[tid] = r0;
    o4[tid + THREADS] = r1;
}

extern "C" void kernel_launch(void* const* d_in, const int* in_sizes, int n_in,
                              void* d_out, int out_size)
{
    const float* X = (const float*)d_in[0];
    float* out = (float*)d_out;
    const int n = in_sizes[0];          // 8*2048*4096
    const int rows = n / D;             // 16384
    entmax_bisect_kernel<<<rows, THREADS>>>(X, out);
}

// round 5
// speedup vs baseline: 1.7060x; 1.1034x over previous
#include <cuda_runtime.h>

// EntmaxBisect: alpha=1.5, 50-iter bisection over last dim (4096), rows = 8*2048 = 16384.
//
// Math reduction: with p = 1/4095, every positive term (Xs_i - t)^p lies in
// (0.975, 1], so sum(Z) >= 1  <=>  count(Xs > t) >= 2  <=>  second_largest(Xs) > t.
// Bisection depends only on the row's top-2; replicated bit-exactly on the
// reference's fp32 lattice (returns the final TESTED t). Top-2 computed on raw
// X and halved afterwards (0.5x is exact & monotone); u = fmaf(0.5,x,-t) is
// bit-identical to (0.5x)-t.
//
// Structure: PERSISTENT CTAs (608 = 4/SM x 152 SM), ~27 rows each, with the
// next row's loads issued BEFORE the current row's barrier-phased reduce/
// bisect/normalize — keeps DRAM streaming through the compute phases.
// The pow is branch-guarded: only ~2 elements per 4096 are active, so nearly
// all warps skip MUFU entirely (round-3 lesson).

#define D        4096
#define THREADS  512
#define NWARPS   16
#define N_ITER   50
#define GRID     608

__global__ __launch_bounds__(THREADS, 4)
void entmax_bisect_kernel(const float* __restrict__ X, float* __restrict__ out,
                          int nrows)
{
    const int tid  = threadIdx.x;
    const int lane = tid & 31;
    const int wid  = tid >> 5;

    __shared__ float sm1[NWARPS];
    __shared__ float sm2[NWARPS];
    __shared__ float ssum[NWARPS];
    __shared__ float sbc;

    const float4* __restrict__ x4 = reinterpret_cast<const float4*>(X);
    float4* __restrict__ o4 = reinterpret_cast<float4*>(out);

    int row = blockIdx.x;
    if (row >= nrows) return;

    // ---- initial load: row `row`, 8 floats/thread (2x float4, coalesced) ----
    size_t base = (size_t)row * (D / 4);
    float4 v0 = x4[base + tid];
    float4 v1 = x4[base + tid + THREADS];

    while (true) {
        const int  nrow  = row + GRID;
        const bool more  = (nrow < nrows);
        // ---- prefetch next row NOW; overlaps all phases below ----
        const int  prow  = more ? nrow : row;
        const size_t pb  = (size_t)prow * (D / 4);
        float4 nv0 = x4[pb + tid];
        float4 nv1 = x4[pb + tid + THREADS];

        // ---- per-thread top-2 of raw X, branchless ----
        float m1 = -__int_as_float(0x7f800000);   // -inf
        float m2 = m1;
        {
            float v, lo;
            v = v0.x; lo = fminf(m1, v); m1 = fmaxf(m1, v); m2 = fmaxf(m2, lo);
            v = v0.y; lo = fminf(m1, v); m1 = fmaxf(m1, v); m2 = fmaxf(m2, lo);
            v = v0.z; lo = fminf(m1, v); m1 = fmaxf(m1, v); m2 = fmaxf(m2, lo);
            v = v0.w; lo = fminf(m1, v); m1 = fmaxf(m1, v); m2 = fmaxf(m2, lo);
            v = v1.x; lo = fminf(m1, v); m1 = fmaxf(m1, v); m2 = fmaxf(m2, lo);
            v = v1.y; lo = fminf(m1, v); m1 = fmaxf(m1, v); m2 = fmaxf(m2, lo);
            v = v1.z; lo = fminf(m1, v); m1 = fmaxf(m1, v); m2 = fmaxf(m2, lo);
            v = v1.w; lo = fminf(m1, v); m1 = fmaxf(m1, v); m2 = fmaxf(m2, lo);
        }

        // ---- warp top-2 reduce ----
        #pragma unroll
        for (int off = 16; off > 0; off >>= 1) {
            float b1 = __shfl_down_sync(0xffffffffu, m1, off);
            float b2 = __shfl_down_sync(0xffffffffu, m2, off);
            float lo = fminf(m1, b1);
            m1 = fmaxf(m1, b1);
            m2 = fmaxf(fmaxf(m2, b2), lo);
        }
        if (lane == 0) { sm1[wid] = m1; sm2[wid] = m2; }
        __syncthreads();                                       // sync1

        if (tid == 0) {
            float M = sm1[0], S = sm2[0];
            #pragma unroll
            for (int w = 1; w < NWARPS; w++) {
                float b1 = sm1[w];
                float lo = fminf(M, b1);
                M = fmaxf(M, b1);
                S = fmaxf(fmaxf(S, sm2[w]), lo);
            }
            M *= 0.5f;                       // exact: top-2 of Xs = 0.5*top-2 of X
            S *= 0.5f;
            // ---- scalar fp32 bisection, bit-faithful to the reference ----
            float tmin = M - 1.0f;
            float tmax = M - 0.015625f;      // M - 4096^(1-1.5), exact constant
            float diff = tmax - tmin;
            float t = tmin;
            #pragma unroll 1
            for (int i = 0; i < N_ITER; i++) {
                diff = diff * 0.5f;
                t = tmin + diff;
                if (S > t) tmin = t;         // == (sum(Z)-1 >= 0)
            }
            sbc = t;                         // final TESTED t, as in reference
        }
        __syncthreads();                                       // sync2

        const float t = sbc;
        const float p = 1.0f / 4095.0f;      // == fp32(1/(d-1))

        // ---- compute Z once in place (branch-guarded fast pow), sum ----
        float lsum = 0.0f;
        {
            float u, z;
            u = fmaf(0.5f, v0.x, -t); z = 0.0f; if (u > 0.0f) z = __powf(u, p); v0.x = z; lsum += z;
            u = fmaf(0.5f, v0.y, -t); z = 0.0f; if (u > 0.0f) z = __powf(u, p); v0.y = z; lsum += z;
            u = fmaf(0.5f, v0.z, -t); z = 0.0f; if (u > 0.0f) z = __powf(u, p); v0.z = z; lsum += z;
            u = fmaf(0.5f, v0.w, -t); z = 0.0f; if (u > 0.0f) z = __powf(u, p); v0.w = z; lsum += z;
            u = fmaf(0.5f, v1.x, -t); z = 0.0f; if (u > 0.0f) z = __powf(u, p); v1.x = z; lsum += z;
            u = fmaf(0.5f, v1.y, -t); z = 0.0f; if (u > 0.0f) z = __powf(u, p); v1.y = z; lsum += z;
            u = fmaf(0.5f, v1.z, -t); z = 0.0f; if (u > 0.0f) z = __powf(u, p); v1.z = z; lsum += z;
            u = fmaf(0.5f, v1.w, -t); z = 0.0f; if (u > 0.0f) z = __powf(u, p); v1.w = z; lsum += z;
        }
        #pragma unroll
        for (int off = 16; off > 0; off >>= 1)
            lsum += __shfl_down_sync(0xffffffffu, lsum, off);
        if (lane == 0) ssum[wid] = lsum;
        __syncthreads();                                       // sync3

        float tot = 0.0f;
        #pragma unroll
        for (int w = 0; w < NWARPS; w++) tot += ssum[w];
        const float inv = 1.0f / tot;

        // ---- write normalized Z, coalesced streaming float4 stores ----
        const size_t ob = (size_t)row * (D / 4);
        float4 r0, r1;
        r0.x = v0.x * inv; r0.y = v0.y * inv; r0.z = v0.z * inv; r0.w = v0.w * inv;
        r1.x = v1.x * inv; r1.y = v1.y * inv; r1.z = v1.z * inv; r1.w = v1.w * inv;
        __stcs(&o4[ob + tid], r0);
        __stcs(&o4[ob + tid + THREADS], r1);

        if (!more) break;
        v0 = nv0; v1 = nv1;
        row = nrow;
    }
}

extern "C" void kernel_launch(void* const* d_in, const int* in_sizes, int n_in,
                              void* d_out, int out_size)
{
    const float* X = (const float*)d_in[0];
    float* out = (float*)d_out;
    const int n = in_sizes[0];          // 8*2048*4096
    const int rows = n / D;             // 16384
    entmax_bisect_kernel<<<GRID, THREADS>>>(X, out, rows);
}